// round 14
// baseline (speedup 1.0000x reference)
#include <cuda_runtime.h>
#include <math.h>

#define MM 48
#define LL 48
#define NN 256
#define NT 256            // threads per CTA (= per sample), 8 warps
#define KPJ 8             // k's per thread (4-aligned contiguous segment)
#define STR2 64           // float2 row stride for ab (16B-aligned)
#define SLOTS (NT * KPJ)  // 2048 checkpoint slots
#define CPB 8             // checkpoint rows: cp[b] = SUF(6b+5)

// smem floats: ab float2[48*64] (=6144 f) | cp[8*2048] | u[48] | prt[72]
#define SM_AB  0
#define SM_CP  (2 * LL * STR2)
#define SM_U   (SM_CP + CPB * SLOTS)
#define SM_PRT (SM_U + LL)
#define SMEMF  (SM_PRT + 72)

typedef unsigned long long u64;

// Accurate f32 sincos: Cody-Waite FMA range reduction + Taylor polys.
// |x| < ~80, ~1-2 ulp, immune to --use_fast_math (no libm).
__device__ __forceinline__ void sincos_acc(float x, float* s, float* c) {
    float kf = rintf(x * 0.63661977236758134f);
    int k = (int)kf;
    float r = fmaf(kf, -1.57079637050628662109375f, x);
    r = fmaf(kf, 4.37113882867379290e-8f, r);
    float r2 = r * r;
    float ps = fmaf(r2, 2.7557314297e-06f, -1.9841270114e-04f);
    ps = fmaf(r2, ps, 8.3333337680e-03f);
    ps = fmaf(r2, ps, -1.6666667163e-01f);
    float sr = fmaf(r * r2, ps, r);
    float pc = fmaf(r2, -2.7557314297e-07f, 2.4760126951e-05f);
    pc = fmaf(r2, pc, -1.3888889225e-03f);
    pc = fmaf(r2, pc, 4.1666667908e-02f);
    float cr = fmaf(r2 * r2, pc, fmaf(r2, -0.5f, 1.0f));
    switch (k & 3) {
        case 0: *s = sr;  *c = cr;  break;
        case 1: *s = cr;  *c = -sr; break;
        case 2: *s = -sr; *c = -cr; break;
        default:*s = -cr; *c = sr;  break;
    }
}

// 8 float2 <-> regs (4x LDS.128); 8 floats <-> regs (2x LDS/STS.128)
__device__ __forceinline__ void ld8f2(const float2* p, float2* v) {
    const float4* q = reinterpret_cast<const float4*>(p);
#pragma unroll
    for (int i = 0; i < 4; i++) {
        float4 t = q[i];
        v[2 * i]     = make_float2(t.x, t.y);
        v[2 * i + 1] = make_float2(t.z, t.w);
    }
}
__device__ __forceinline__ void ld8(const float* p, float* v) {
    const float4* q = reinterpret_cast<const float4*>(p);
    float4 x = q[0], y = q[1];
    v[0] = x.x; v[1] = x.y; v[2] = x.z; v[3] = x.w;
    v[4] = y.x; v[5] = y.y; v[6] = y.z; v[7] = y.w;
}
__device__ __forceinline__ void st8(float* p, const float* v) {
    float4* q = reinterpret_cast<float4*>(p);
    q[0] = make_float4(v[0], v[1], v[2], v[3]);
    q[1] = make_float4(v[4], v[5], v[6], v[7]);
}

__global__ __launch_bounds__(NT, 2) void fused_kernel(
    const float* __restrict__ inp,      // (N,L)
    const float* __restrict__ theta,    // (L,M)
    const float* __restrict__ coef,     // (M,)
    const float* __restrict__ rand_u,   // (L,N)
    float* __restrict__ out)            // N*L bits then N probs
{
    extern __shared__ float sm[];
    float2* ab  = reinterpret_cast<float2*>(sm + SM_AB);  // [l*STR2 + k]
    float*  cp  = sm + SM_CP;
    float*  ush = sm + SM_U;
    float*  prt = sm + SM_PRT;

    const int n = blockIdx.x, tid = threadIdx.x;
    const int lane = tid & 31, wid = tid >> 5;

    // ---- Phase A: AoS embedding tile (f32 rounding matches reference) ----
    const float PI2F = 1.57079637050628662109375f;
#pragma unroll
    for (int e = tid; e < LL * STR2; e += NT) {
        int l = e / STR2, c = e - l * STR2;
        float a = 0.f, b = 0.f;
        if (c < MM) {
            float ang = inp[n * LL + l] * ((float)(c + 1) * PI2F);
            float sv, cv; sincos_acc(ang, &sv, &cv);
            float st, ct; sincos_acc(theta[l * MM + c], &st, &ct);
            float cf = coef[c];
            a = cf * (ct * cv - st * sv);
            b = cf * (st * cv + ct * sv);
        }
        ab[e] = make_float2(a, b);
    }
    if (tid < LL) ush[tid] = rand_u[tid * NN + n];
    __syncthreads();

    // ---- segment decode: thread owns m and k in [kst, kst+7], kst % 4 == 0 ----
    int m = 47, kst = 48;                 // default: idle thread (reads zero pad)
    {
        int t = tid;
        for (int mm = 0; mm < MM; mm++) {
            int s = mm & ~3;
            int nseg = (MM - s + KPJ - 1) / KPJ;
            if (t < nseg) { m = mm; kst = s + t * KPJ; break; }
            t -= nseg;
        }
    }
    const bool wact = __ballot_sync(0xffffffffu, kst < MM) != 0u;   // warp-uniform

    // ---- Phase B: backward scan; checkpoint SUF (weight baked) at l%6==5 ----
    if (wact) {
        float run[KPJ];
#pragma unroll
        for (int j = 0; j < KPJ; j++) {
            int k = kst + j;
            run[j] = (k < m || k >= MM) ? 0.f : ((k == m) ? 1.f : 2.f);
        }
        for (int l = LL - 1; l >= 0; l--) {
            if ((l % 6) == 5)
                st8(cp + (l / 6) * SLOTS + tid * KPJ, run);
            float2 mv = ab[l * STR2 + m];
            float2 kv[KPJ];
            ld8f2(ab + l * STR2 + kst, kv);
#pragma unroll
            for (int j = 0; j < KPJ; j++)
                run[j] *= fmaf(mv.x, kv[j].x, mv.y * kv[j].y);
        }
    }
    // cp rows written and read by the same thread — no barrier needed.

    float P[KPJ];
#pragma unroll
    for (int j = 0; j < KPJ; j++)
        P[j] = (kst + j < m || kst + j >= MM) ? 0.f : 1.f;

    // suffix rows for block b: r5 = SUF(6b+5) = cp[b];
    // r3 = r5*d(6b+5)*d(6b+4);  r1 = r3*d(6b+3)*d(6b+2)
    float r1[KPJ], r3[KPJ], r5[KPJ];
    auto dotsite = [&](int l, float* dst, const float* src) {
        float2 mv = ab[l * STR2 + m];
        float2 kv[KPJ];
        ld8f2(ab + l * STR2 + kst, kv);
#pragma unroll
        for (int j = 0; j < KPJ; j++)
            dst[j] = src[j] * fmaf(mv.x, kv[j].x, mv.y * kv[j].y);
    };
    auto rebuild = [&](int b) {
        ld8(cp + b * SLOTS + tid * KPJ, r5);
        dotsite(6 * b + 5, r3, r5);
        dotsite(6 * b + 4, r3, r3);
        dotsite(6 * b + 3, r1, r3);
        dotsite(6 * b + 2, r1, r1);
    };
    if (wact) rebuild(0);

    float denom0 = 1.f;
    int Kexp = 0;
    u64 bits = 0ull;

    // ---- Phase C: 24 two-site rounds (4 speculative sums, 1 barrier each) ----
    // T_{b1,b2} = sum_j P*cc1_{b1}*cc2_{b2}*SUF(l0+1);  S_b(l0) = T_{b,0}+T_{b,1}.
    auto round2 = [&](int l0, const float* suf, int bnext) {
        const int par = ((l0 >> 1) & 1) * 32;
        float q00[KPJ], q01[KPJ], q10[KPJ], q11[KPJ];
        if (wact) {
            float2 abm1 = ab[l0 * STR2 + m];
            float2 abm2 = ab[(l0 + 1) * STR2 + m];
            float2 k1[KPJ], k2[KPJ];
            ld8f2(ab + l0 * STR2 + kst, k1);
            ld8f2(ab + (l0 + 1) * STR2 + kst, k2);

            float t00 = 0.f, t01 = 0.f, t10 = 0.f, t11 = 0.f;
#pragma unroll
            for (int j = 0; j < KPJ; j++) {
                float aa1 = abm1.x * k1[j].x, bb1 = abm1.y * k1[j].y;
                float aa2 = abm2.x * k2[j].x, bb2 = abm2.y * k2[j].y;
                float pa = P[j] * aa1, pb = P[j] * bb1;
                q00[j] = pa * aa2; q01[j] = pa * bb2;
                q10[j] = pb * aa2; q11[j] = pb * bb2;
                t00 = fmaf(q00[j], suf[j], t00);
                t01 = fmaf(q01[j], suf[j], t01);
                t10 = fmaf(q10[j], suf[j], t10);
                t11 = fmaf(q11[j], suf[j], t11);
            }
#pragma unroll
            for (int o = 16; o; o >>= 1) {
                t00 += __shfl_xor_sync(0xffffffffu, t00, o);
                t01 += __shfl_xor_sync(0xffffffffu, t01, o);
                t10 += __shfl_xor_sync(0xffffffffu, t10, o);
                t11 += __shfl_xor_sync(0xffffffffu, t11, o);
            }
            if (lane == 0) {
                prt[par + wid]      = t00;
                prt[par + 8 + wid]  = t01;
                prt[par + 16 + wid] = t10;
                prt[par + 24 + wid] = t11;
            }
            if (bnext >= 0) rebuild(bnext);    // fills bar wait, bit-independent
        }
        __syncthreads();

        if (wact) {
            // redundant decisions on active warps (identical values)
            const float4* q = reinterpret_cast<const float4*>(prt + par);
            float4 v0, v1;
            v0 = q[0]; v1 = q[1];
            float T00 = ((v0.x + v0.y) + (v0.z + v0.w)) + ((v1.x + v1.y) + (v1.z + v1.w));
            v0 = q[2]; v1 = q[3];
            float T01 = ((v0.x + v0.y) + (v0.z + v0.w)) + ((v1.x + v1.y) + (v1.z + v1.w));
            v0 = q[4]; v1 = q[5];
            float T10 = ((v0.x + v0.y) + (v0.z + v0.w)) + ((v1.x + v1.y) + (v1.z + v1.w));
            v0 = q[6]; v1 = q[7];
            float T11 = ((v0.x + v0.y) + (v0.z + v0.w)) + ((v1.x + v1.y) + (v1.z + v1.w));

            float uv1 = ush[l0], uv2 = ush[l0 + 1];
            float S1  = T10 + T11;
            float den1 = fabsf((T00 + T01) + S1);
            int b1 = (uv1 * den1 < fabsf(S1)) ? 1 : 0;
            if (l0 == 0) denom0 = den1;
            float S0p = b1 ? T10 : T00;
            float S1p = b1 ? T11 : T01;
            float den2 = fabsf(S0p + S1p);
            int b2 = (uv2 * den2 < fabsf(S1p)) ? 1 : 0;
            int eb = (__float_as_int(den2) >> 23) & 0xFF;   // exact 2^-k renorm
            int kk = eb ? (eb - 127) >> 1 : 0;
            Kexp += kk;
            float scale = __int_as_float((127 - kk) << 23);
            bits |= ((u64)b1 << l0) | ((u64)b2 << (l0 + 1));
#pragma unroll
            for (int j = 0; j < KPJ; j++) {                 // select + scale only
                float qa = b2 ? q01[j] : q00[j];
                float qb = b2 ? q11[j] : q10[j];
                P[j] = (b1 ? qb : qa) * scale;
            }
        }
    };

#pragma unroll 1
    for (int b = 0; b < CPB; b++) {
        round2(6 * b,     r1, -1);
        round2(6 * b + 2, r3, -1);
        round2(6 * b + 4, r5, (b + 1 < CPB) ? b + 1 : -1);
    }

    // ---- epilogue: final inner = sum w*P (true value * 2^Kexp), outputs ----
    float sf = 0.f;
#pragma unroll
    for (int j = 0; j < KPJ; j++) {
        int k = kst + j;
        float w = (k < m || k >= MM) ? 0.f : ((k == m) ? 1.f : 2.f);
        sf += w * P[j];
    }
#pragma unroll
    for (int o = 16; o; o >>= 1) sf += __shfl_xor_sync(0xffffffffu, sf, o);
    if (lane == 0) prt[64 + wid] = sf;
    __syncthreads();

    if (tid < LL) out[n * LL + tid] = (float)((bits >> tid) & 1ull);
    if (tid == 0) {
        float t = 0.f;
#pragma unroll
        for (int w = 0; w < 8; w++) t += prt[64 + w];
        double pmv = ldexp(fabs((double)t), Kexp) / (double)denom0;
        out[NN * LL + n] = (float)pmv;
    }
}

extern "C" void kernel_launch(void* const* d_in, const int* in_sizes, int n_in,
                              void* d_out, int out_size) {
    const float* inp    = (const float*)d_in[0];   // (N,L)
    const float* theta  = (const float*)d_in[1];   // (L,M)
    const float* coef   = (const float*)d_in[2];   // (M,)
    const float* rand_u = (const float*)d_in[3];   // (L,N)
    float* out = (float*)d_out;

    static int smem_set = 0;
    if (!smem_set) {
        cudaFuncSetAttribute(fused_kernel,
                             cudaFuncAttributeMaxDynamicSharedMemorySize,
                             SMEMF * (int)sizeof(float));
        smem_set = 1;
    }
    fused_kernel<<<NN, NT, SMEMF * sizeof(float)>>>(inp, theta, coef, rand_u, out);
}

// round 15
// speedup vs baseline: 1.4730x; 1.4730x over previous
#include <cuda_runtime.h>
#include <math.h>

#define MM 48
#define LL 48
#define NN 256
#define NT 128            // threads per CTA (= per sample)
#define KPJ 12            // k's per thread (4-aligned contiguous segment)
#define STR2 64           // float2 row stride for ab (16B-aligned)
#define SLOTS (NT * KPJ)  // 1536 checkpoint slots
#define CPB 12            // checkpoint rows: cp[b] = SUF(4b+3)

// smem floats: ab float2[48*64] (=6144 f) | cp[12*1536] | u[48] | prt[40]
#define SM_AB  0
#define SM_CP  (2 * LL * STR2)
#define SM_U   (SM_CP + CPB * SLOTS)
#define SM_PRT (SM_U + LL)
#define SMEMF  (SM_PRT + 40)

typedef unsigned long long u64;

// Accurate f32 sincos: Cody-Waite FMA range reduction + Taylor polys.
// |x| < ~80, ~1-2 ulp, immune to --use_fast_math (no libm).
__device__ __forceinline__ void sincos_acc(float x, float* s, float* c) {
    float kf = rintf(x * 0.63661977236758134f);
    int k = (int)kf;
    float r = fmaf(kf, -1.57079637050628662109375f, x);
    r = fmaf(kf, 4.37113882867379290e-8f, r);
    float r2 = r * r;
    float ps = fmaf(r2, 2.7557314297e-06f, -1.9841270114e-04f);
    ps = fmaf(r2, ps, 8.3333337680e-03f);
    ps = fmaf(r2, ps, -1.6666667163e-01f);
    float sr = fmaf(r * r2, ps, r);
    float pc = fmaf(r2, -2.7557314297e-07f, 2.4760126951e-05f);
    pc = fmaf(r2, pc, -1.3888889225e-03f);
    pc = fmaf(r2, pc, 4.1666667908e-02f);
    float cr = fmaf(r2 * r2, pc, fmaf(r2, -0.5f, 1.0f));
    switch (k & 3) {
        case 0: *s = sr;  *c = cr;  break;
        case 1: *s = cr;  *c = -sr; break;
        case 2: *s = -sr; *c = -cr; break;
        default:*s = -cr; *c = sr;  break;
    }
}

// 12 float2 <-> regs (6x LDS.128); 12 floats <-> regs (3x LDS/STS.128)
__device__ __forceinline__ void ld12f2(const float2* p, float2* v) {
    const float4* q = reinterpret_cast<const float4*>(p);
#pragma unroll
    for (int i = 0; i < 6; i++) {
        float4 t = q[i];
        v[2 * i]     = make_float2(t.x, t.y);
        v[2 * i + 1] = make_float2(t.z, t.w);
    }
}
__device__ __forceinline__ void ld12(const float* p, float* v) {
    const float4* q = reinterpret_cast<const float4*>(p);
    float4 x = q[0], y = q[1], z = q[2];
    v[0] = x.x; v[1] = x.y; v[2]  = x.z; v[3]  = x.w;
    v[4] = y.x; v[5] = y.y; v[6]  = y.z; v[7]  = y.w;
    v[8] = z.x; v[9] = z.y; v[10] = z.z; v[11] = z.w;
}
__device__ __forceinline__ void st12(float* p, const float* v) {
    float4* q = reinterpret_cast<float4*>(p);
    q[0] = make_float4(v[0], v[1], v[2],  v[3]);
    q[1] = make_float4(v[4], v[5], v[6],  v[7]);
    q[2] = make_float4(v[8], v[9], v[10], v[11]);
}

__global__ __launch_bounds__(NT, 2) void fused_kernel(
    const float* __restrict__ inp,      // (N,L)
    const float* __restrict__ theta,    // (L,M)
    const float* __restrict__ coef,     // (M,)
    const float* __restrict__ rand_u,   // (L,N)
    float* __restrict__ out)            // N*L bits then N probs
{
    extern __shared__ float sm[];
    float2* ab  = reinterpret_cast<float2*>(sm + SM_AB);  // [l*STR2 + k]
    float*  cp  = sm + SM_CP;
    float*  ush = sm + SM_U;
    float*  prt = sm + SM_PRT;

    const int n = blockIdx.x, tid = threadIdx.x;
    const int lane = tid & 31, wid = tid >> 5;

    // ---- Phase A: AoS embedding tile (f32 rounding matches reference) ----
    const float PI2F = 1.57079637050628662109375f;
#pragma unroll
    for (int e = tid; e < LL * STR2; e += NT) {
        int l = e / STR2, c = e - l * STR2;
        float a = 0.f, b = 0.f;
        if (c < MM) {
            float ang = inp[n * LL + l] * ((float)(c + 1) * PI2F);
            float sv, cv; sincos_acc(ang, &sv, &cv);
            float st, ct; sincos_acc(theta[l * MM + c], &st, &ct);
            float cf = coef[c];
            a = cf * (ct * cv - st * sv);
            b = cf * (st * cv + ct * sv);
        }
        ab[e] = make_float2(a, b);
    }
    if (tid < LL) ush[tid] = rand_u[tid * NN + n];
    __syncthreads();

    // ---- segment decode: thread owns m and k in [kst, kst+11], kst % 4 == 0 ----
    int m = 47, kst = 48;                 // default: idle thread (reads zero pad)
    {
        int t = tid;
        for (int mm = 0; mm < MM; mm++) {
            int s = mm & ~3;
            int nseg = (MM - s + KPJ - 1) / KPJ;
            if (t < nseg) { m = mm; kst = s + t * KPJ; break; }
            t -= nseg;
        }
    }

    // ---- Phase B: backward scan; checkpoint SUF (weight baked) at l%4==3 ----
    {
        float run[KPJ];
#pragma unroll
        for (int j = 0; j < KPJ; j++) {
            int k = kst + j;
            run[j] = (k < m || k >= MM) ? 0.f : ((k == m) ? 1.f : 2.f);
        }
        for (int l = LL - 1; l >= 0; l--) {
            if ((l & 3) == 3)
                st12(cp + (l >> 2) * SLOTS + tid * KPJ, run);
            float2 mv = ab[l * STR2 + m];
            float2 kv[KPJ];
            ld12f2(ab + l * STR2 + kst, kv);
#pragma unroll
            for (int j = 0; j < KPJ; j++)
                run[j] *= fmaf(mv.x, kv[j].x, mv.y * kv[j].y);
        }
    }
    // cp rows written and read by the same thread — no barrier needed.

    float P[KPJ];
#pragma unroll
    for (int j = 0; j < KPJ; j++)
        P[j] = (kst + j < m || kst + j >= MM) ? 0.f : 1.f;

    // load cc products (aa,bb at sites l0 and l0+1) for a round
    auto loadcc = [&](int l0, float* c1a, float* c1b, float* c2a, float* c2b) {
        float2 m1 = ab[l0 * STR2 + m];
        float2 m2 = ab[(l0 + 1) * STR2 + m];
        float2 k1[KPJ], k2[KPJ];
        ld12f2(ab + l0 * STR2 + kst, k1);
        ld12f2(ab + (l0 + 1) * STR2 + kst, k2);
#pragma unroll
        for (int j = 0; j < KPJ; j++) {
            c1a[j] = m1.x * k1[j].x; c1b[j] = m1.y * k1[j].y;
            c2a[j] = m2.x * k2[j].x; c2b[j] = m2.y * k2[j].y;
        }
    };
    // d(l) multiply: dst = src * (aa+bb at site l)
    auto dotsite = [&](int l, float* dst, const float* src) {
        float2 mv = ab[l * STR2 + m];
        float2 kv[KPJ];
        ld12f2(ab + l * STR2 + kst, kv);
#pragma unroll
        for (int j = 0; j < KPJ; j++)
            dst[j] = src[j] * fmaf(mv.x, kv[j].x, mv.y * kv[j].y);
    };

    // suffix rows: r3 = SUF(4b+3) = cp[b];  r1 = SUF(4b+1) = r3*d(4b+3)*d(4b+2)
    float r1[KPJ], r3[KPJ];
    ld12(cp + tid * KPJ, r3);
    dotsite(3, r1, r3);
    dotsite(2, r1, r1);

    // cc double buffers: ccA for rounds l0=4b, ccB for rounds l0=4b+2
    float Aa1[KPJ], Ab1[KPJ], Aa2[KPJ], Ab2[KPJ];
    float Ba1[KPJ], Bb1[KPJ], Ba2[KPJ], Bb2[KPJ];
    loadcc(0, Aa1, Ab1, Aa2, Ab2);

    float denom0 = 1.f;
    int Kexp = 0;
    u64 bits = 0ull;

    // ---- Phase C: 24 two-site rounds; cc prefetched pre-barrier ----
    // T_{b1,b2} = sum_j (P*cc1_{b1}*suf)*cc2_{b2};  S_b(l0) = T_{b,0}+T_{b,1}.
    auto round2 = [&](int l0, const float* suf,
                      const float* c1a, const float* c1b,
                      const float* c2a, const float* c2b,
                      int window) {
        float uv1 = ush[l0], uv2 = ush[l0 + 1];
        float t00 = 0.f, t01 = 0.f, t10 = 0.f, t11 = 0.f;
#pragma unroll
        for (int j = 0; j < KPJ; j++) {
            float pa = P[j] * c1a[j], pb = P[j] * c1b[j];
            float pas = pa * suf[j], pbs = pb * suf[j];
            t00 = fmaf(pas, c2a[j], t00);
            t01 = fmaf(pas, c2b[j], t01);
            t10 = fmaf(pbs, c2a[j], t10);
            t11 = fmaf(pbs, c2b[j], t11);
        }
#pragma unroll
        for (int o = 16; o; o >>= 1) {
            t00 += __shfl_xor_sync(0xffffffffu, t00, o);
            t01 += __shfl_xor_sync(0xffffffffu, t01, o);
            t10 += __shfl_xor_sync(0xffffffffu, t10, o);
            t11 += __shfl_xor_sync(0xffffffffu, t11, o);
        }
        const int par = ((l0 >> 1) & 1) * 16;
        if (lane == 0) {
            prt[par + wid]      = t00;
            prt[par + 4 + wid]  = t01;
            prt[par + 8 + wid]  = t10;
            prt[par + 12 + wid] = t11;
        }

        // pre-barrier window: bit-independent prefetch for FUTURE rounds
        const int b = l0 >> 2;
        if (window == 0) {
            // round(4b): load ccB for round(4b+2); r1' = SUF(4b+5) for next block
            loadcc(l0 + 2, Ba1, Bb1, Ba2, Bb2);
            if (b + 1 < CPB) {
                ld12(cp + (b + 1) * SLOTS + tid * KPJ, r1);   // SUF(4b+7)
                dotsite(4 * b + 7, r1, r1);
                dotsite(4 * b + 6, r1, r1);                   // SUF(4b+5)
            }
        } else if (b + 1 < CPB) {
            // round(4b+2): load ccA for round(4b+4); r3' = cp[b+1]
            loadcc(l0 + 2, Aa1, Ab1, Aa2, Ab2);
            ld12(cp + (b + 1) * SLOTS + tid * KPJ, r3);
        }
        __syncthreads();

        // redundant decisions (identical on all threads)
        const float4* q = reinterpret_cast<const float4*>(prt + par);
        float4 v;
        v = q[0]; float T00 = (v.x + v.y) + (v.z + v.w);
        v = q[1]; float T01 = (v.x + v.y) + (v.z + v.w);
        v = q[2]; float T10 = (v.x + v.y) + (v.z + v.w);
        v = q[3]; float T11 = (v.x + v.y) + (v.z + v.w);

        float S1  = T10 + T11;
        float den1 = fabsf((T00 + T01) + S1);
        int b1 = (uv1 * den1 < fabsf(S1)) ? 1 : 0;
        if (l0 == 0) denom0 = den1;
        float S0p = b1 ? T10 : T00;
        float S1p = b1 ? T11 : T01;
        float den2 = fabsf(S0p + S1p);
        int b2 = (uv2 * den2 < fabsf(S1p)) ? 1 : 0;
        int eb = (__float_as_int(den2) >> 23) & 0xFF;   // exact 2^-k renorm
        int kk = eb ? (eb - 127) >> 1 : 0;
        Kexp += kk;
        float scale = __int_as_float((127 - kk) << 23);
        bits |= ((u64)b1 << l0) | ((u64)b2 << (l0 + 1));
#pragma unroll
        for (int j = 0; j < KPJ; j++) {                 // recompute from live cc
            float c1s = b1 ? c1b[j] : c1a[j];
            float c2s = b2 ? c2b[j] : c2a[j];
            P[j] = ((P[j] * c1s) * c2s) * scale;
        }
    };

#pragma unroll 1
    for (int b = 0; b < CPB; b++) {
        round2(4 * b,     r1, Aa1, Ab1, Aa2, Ab2, 0);
        round2(4 * b + 2, r3, Ba1, Bb1, Ba2, Bb2, 1);
    }

    // ---- epilogue: final inner = sum w*P (true value * 2^Kexp), outputs ----
    float sf = 0.f;
#pragma unroll
    for (int j = 0; j < KPJ; j++) {
        int k = kst + j;
        float w = (k < m || k >= MM) ? 0.f : ((k == m) ? 1.f : 2.f);
        sf += w * P[j];
    }
#pragma unroll
    for (int o = 16; o; o >>= 1) sf += __shfl_xor_sync(0xffffffffu, sf, o);
    if (lane == 0) prt[32 + wid] = sf;
    __syncthreads();

    if (tid < LL) out[n * LL + tid] = (float)((bits >> tid) & 1ull);
    if (tid == 0) {
        double Sf = (double)((prt[32] + prt[33]) + (prt[34] + prt[35]));
        double pmv = ldexp(fabs(Sf), Kexp) / (double)denom0;
        out[NN * LL + n] = (float)pmv;
    }
}

extern "C" void kernel_launch(void* const* d_in, const int* in_sizes, int n_in,
                              void* d_out, int out_size) {
    const float* inp    = (const float*)d_in[0];   // (N,L)
    const float* theta  = (const float*)d_in[1];   // (L,M)
    const float* coef   = (const float*)d_in[2];   // (M,)
    const float* rand_u = (const float*)d_in[3];   // (L,N)
    float* out = (float*)d_out;

    static int smem_set = 0;
    if (!smem_set) {
        cudaFuncSetAttribute(fused_kernel,
                             cudaFuncAttributeMaxDynamicSharedMemorySize,
                             SMEMF * (int)sizeof(float));
        smem_set = 1;
    }
    fused_kernel<<<NN, NT, SMEMF * sizeof(float)>>>(inp, theta, coef, rand_u, out);
}

// round 16
// speedup vs baseline: 1.6221x; 1.1013x over previous
#include <cuda_runtime.h>
#include <math.h>

#define MM 48
#define LL 48
#define NN 256
#define NT 128            // threads per CTA (= per sample)
#define KPJ 12            // k's per thread (4-aligned contiguous segment)
#define STR2 64           // float2 row stride for ab (16B-aligned)
#define SLOTS (NT * KPJ)  // 1536 checkpoint slots
#define CPB 12            // checkpoint rows: cp[b] = SUF(4b+3)

// smem floats: ab float2[48*64] (=6144 f) | cp[12*1536] | u[48] | prt[40]
#define SM_AB  0
#define SM_CP  (2 * LL * STR2)
#define SM_U   (SM_CP + CPB * SLOTS)
#define SM_PRT (SM_U + LL)
#define SMEMF  (SM_PRT + 40)

typedef unsigned long long u64;

// Accurate f32 sincos: Cody-Waite FMA range reduction + Taylor polys.
// |x| < ~80, ~1-2 ulp, immune to --use_fast_math (no libm).
__device__ __forceinline__ void sincos_acc(float x, float* s, float* c) {
    float kf = rintf(x * 0.63661977236758134f);
    int k = (int)kf;
    float r = fmaf(kf, -1.57079637050628662109375f, x);
    r = fmaf(kf, 4.37113882867379290e-8f, r);
    float r2 = r * r;
    float ps = fmaf(r2, 2.7557314297e-06f, -1.9841270114e-04f);
    ps = fmaf(r2, ps, 8.3333337680e-03f);
    ps = fmaf(r2, ps, -1.6666667163e-01f);
    float sr = fmaf(r * r2, ps, r);
    float pc = fmaf(r2, -2.7557314297e-07f, 2.4760126951e-05f);
    pc = fmaf(r2, pc, -1.3888889225e-03f);
    pc = fmaf(r2, pc, 4.1666667908e-02f);
    float cr = fmaf(r2 * r2, pc, fmaf(r2, -0.5f, 1.0f));
    switch (k & 3) {
        case 0: *s = sr;  *c = cr;  break;
        case 1: *s = cr;  *c = -sr; break;
        case 2: *s = -sr; *c = -cr; break;
        default:*s = -cr; *c = sr;  break;
    }
}

// 12 float2 <-> regs (6x LDS.128); 12 floats <-> regs (3x LDS/STS.128)
__device__ __forceinline__ void ld12f2(const float2* p, float2* v) {
    const float4* q = reinterpret_cast<const float4*>(p);
#pragma unroll
    for (int i = 0; i < 6; i++) {
        float4 t = q[i];
        v[2 * i]     = make_float2(t.x, t.y);
        v[2 * i + 1] = make_float2(t.z, t.w);
    }
}
__device__ __forceinline__ void ld12(const float* p, float* v) {
    const float4* q = reinterpret_cast<const float4*>(p);
    float4 x = q[0], y = q[1], z = q[2];
    v[0] = x.x; v[1] = x.y; v[2]  = x.z; v[3]  = x.w;
    v[4] = y.x; v[5] = y.y; v[6]  = y.z; v[7]  = y.w;
    v[8] = z.x; v[9] = z.y; v[10] = z.z; v[11] = z.w;
}
__device__ __forceinline__ void st12(float* p, const float* v) {
    float4* q = reinterpret_cast<float4*>(p);
    q[0] = make_float4(v[0], v[1], v[2],  v[3]);
    q[1] = make_float4(v[4], v[5], v[6],  v[7]);
    q[2] = make_float4(v[8], v[9], v[10], v[11]);
}

__global__ __launch_bounds__(NT, 2) void fused_kernel(
    const float* __restrict__ inp,      // (N,L)
    const float* __restrict__ theta,    // (L,M)
    const float* __restrict__ coef,     // (M,)
    const float* __restrict__ rand_u,   // (L,N)
    float* __restrict__ out)            // N*L bits then N probs
{
    extern __shared__ float sm[];
    float2* ab  = reinterpret_cast<float2*>(sm + SM_AB);  // [l*STR2 + k]
    float*  cp  = sm + SM_CP;
    float*  ush = sm + SM_U;
    float*  prt = sm + SM_PRT;

    const int n = blockIdx.x, tid = threadIdx.x;
    const int lane = tid & 31, wid = tid >> 5;

    // ---- Phase A: AoS embedding tile (f32 rounding matches reference) ----
    const float PI2F = 1.57079637050628662109375f;
#pragma unroll
    for (int e = tid; e < LL * STR2; e += NT) {
        int l = e / STR2, c = e - l * STR2;
        float a = 0.f, b = 0.f;
        if (c < MM) {
            float ang = inp[n * LL + l] * ((float)(c + 1) * PI2F);
            float sv, cv; sincos_acc(ang, &sv, &cv);
            float st, ct; sincos_acc(theta[l * MM + c], &st, &ct);
            float cf = coef[c];
            a = cf * (ct * cv - st * sv);
            b = cf * (st * cv + ct * sv);
        }
        ab[e] = make_float2(a, b);
    }
    if (tid < LL) ush[tid] = rand_u[tid * NN + n];
    __syncthreads();

    // ---- segment decode: thread owns m and k in [kst, kst+11], kst % 4 == 0 ----
    int m = 47, kst = 48;                 // default: idle thread (reads zero pad)
    {
        int t = tid;
        for (int mm = 0; mm < MM; mm++) {
            int s = mm & ~3;
            int nseg = (MM - s + KPJ - 1) / KPJ;
            if (t < nseg) { m = mm; kst = s + t * KPJ; break; }
            t -= nseg;
        }
    }

    // ---- Phase B: backward scan; checkpoint SUF (weight baked) at l%4==3 ----
    {
        float run[KPJ];
#pragma unroll
        for (int j = 0; j < KPJ; j++) {
            int k = kst + j;
            run[j] = (k < m || k >= MM) ? 0.f : ((k == m) ? 1.f : 2.f);
        }
        for (int l = LL - 1; l >= 0; l--) {
            if ((l & 3) == 3)
                st12(cp + (l >> 2) * SLOTS + tid * KPJ, run);
            float2 mv = ab[l * STR2 + m];
            float2 kv[KPJ];
            ld12f2(ab + l * STR2 + kst, kv);
#pragma unroll
            for (int j = 0; j < KPJ; j++)
                run[j] *= fmaf(mv.x, kv[j].x, mv.y * kv[j].y);
        }
    }
    // cp rows written and read by the same thread — no barrier needed.

    float P[KPJ];
#pragma unroll
    for (int j = 0; j < KPJ; j++)
        P[j] = (kst + j < m || kst + j >= MM) ? 0.f : 1.f;

    // suffix registers: r3 = SUF(4b+3) = cp[b]; r1 = SUF(4b+1) = r3*d(4b+3)*d(4b+2)
    float r1[KPJ], r3[KPJ];
    auto rebuild = [&](int b) {
        ld12(cp + b * SLOTS + tid * KPJ, r3);
        float2 kv[KPJ];
        int l = 4 * b + 3;
        float2 mv = ab[l * STR2 + m];
        ld12f2(ab + l * STR2 + kst, kv);
#pragma unroll
        for (int j = 0; j < KPJ; j++)
            r1[j] = r3[j] * fmaf(mv.x, kv[j].x, mv.y * kv[j].y);
        l = 4 * b + 2;
        mv = ab[l * STR2 + m];
        ld12f2(ab + l * STR2 + kst, kv);
#pragma unroll
        for (int j = 0; j < KPJ; j++)
            r1[j] *= fmaf(mv.x, kv[j].x, mv.y * kv[j].y);
    };
    rebuild(0);

    float denom0 = 1.f;
    int Kexp = 0;
    u64 bits = 0ull;

    // ---- Phase C: 24 two-site rounds (4 speculative sums, 1 barrier each) ----
    // Value-rotated butterfly: 6 SHFLs reduce all four sums.
    // T_{b1,b2} = sum_j P*cc1_{b1}*cc2_{b2}*SUF(l0+1);  S_b(l0) = T_{b,0}+T_{b,1}.
    auto round2 = [&](int l0, const float* suf, int bnext) {
        float uv1 = ush[l0], uv2 = ush[l0 + 1];
        float2 abm1 = ab[l0 * STR2 + m];
        float2 abm2 = ab[(l0 + 1) * STR2 + m];
        float2 k1[KPJ], k2[KPJ];
        ld12f2(ab + l0 * STR2 + kst, k1);
        ld12f2(ab + (l0 + 1) * STR2 + kst, k2);

        float q00[KPJ], q01[KPJ], q10[KPJ], q11[KPJ];
        float t00 = 0.f, t01 = 0.f, t10 = 0.f, t11 = 0.f;
#pragma unroll
        for (int j = 0; j < KPJ; j++) {
            float aa1 = abm1.x * k1[j].x, bb1 = abm1.y * k1[j].y;
            float aa2 = abm2.x * k2[j].x, bb2 = abm2.y * k2[j].y;
            float pa = P[j] * aa1, pb = P[j] * bb1;
            q00[j] = pa * aa2; q01[j] = pa * bb2;
            q10[j] = pb * aa2; q11[j] = pb * bb2;
            t00 = fmaf(q00[j], suf[j], t00);
            t01 = fmaf(q01[j], suf[j], t01);
            t10 = fmaf(q10[j], suf[j], t10);
            t11 = fmaf(q11[j], suf[j], t11);
        }
        // value-rotated reduction: 6 SHFLs total for 4 sums
        {
            const int p = lane & 1, q2 = (lane >> 1) & 1;
            // level 1 (xor 1): even lanes keep {t00,t01}, odd keep {t10,t11}
            float k1v = p ? t10 : t00;
            float k2v = p ? t11 : t01;
            float s1v = p ? t00 : t10;
            float s2v = p ? t01 : t11;
            k1v += __shfl_xor_sync(0xffffffffu, s1v, 1);
            k2v += __shfl_xor_sync(0xffffffffu, s2v, 1);
            // level 2 (xor 2): q2=0 keeps k1v-class, q2=1 keeps k2v-class
            float kv = q2 ? k2v : k1v;
            float sv = q2 ? k1v : k2v;
            kv += __shfl_xor_sync(0xffffffffu, sv, 2);
            // levels 3-5: plain reduce of the single kept value
            kv += __shfl_xor_sync(0xffffffffu, kv, 4);
            kv += __shfl_xor_sync(0xffffffffu, kv, 8);
            kv += __shfl_xor_sync(0xffffffffu, kv, 16);
            // lane&3 -> sum index: 0->T00, 1->T10, 2->T01, 3->T11
            const int par0 = ((l0 >> 1) & 1) * 16;
            if (lane < 4) {
                int sidx = ((lane & 1) << 1) | ((lane >> 1) & 1);  // 0,2,1,3
                prt[par0 + sidx * 4 + wid] = kv;
            }
        }
        if (bnext >= 0) rebuild(bnext);    // fills bar wait, bit-independent
        __syncthreads();

        // redundant decisions (identical on all threads)
        const int par = ((l0 >> 1) & 1) * 16;
        const float4* q = reinterpret_cast<const float4*>(prt + par);
        float4 v;
        v = q[0]; float T00 = (v.x + v.y) + (v.z + v.w);
        v = q[1]; float T01 = (v.x + v.y) + (v.z + v.w);
        v = q[2]; float T10 = (v.x + v.y) + (v.z + v.w);
        v = q[3]; float T11 = (v.x + v.y) + (v.z + v.w);

        float S1  = T10 + T11;
        float den1 = fabsf((T00 + T01) + S1);
        int b1 = (uv1 * den1 < fabsf(S1)) ? 1 : 0;
        if (l0 == 0) denom0 = den1;
        float S0p = b1 ? T10 : T00;
        float S1p = b1 ? T11 : T01;
        float den2 = fabsf(S0p + S1p);
        int b2 = (uv2 * den2 < fabsf(S1p)) ? 1 : 0;
        int eb = (__float_as_int(den2) >> 23) & 0xFF;   // exact 2^-k renorm
        int kk = eb ? (eb - 127) >> 1 : 0;
        Kexp += kk;
        float scale = __int_as_float((127 - kk) << 23);
        bits |= ((u64)b1 << l0) | ((u64)b2 << (l0 + 1));
#pragma unroll
        for (int j = 0; j < KPJ; j++) {                 // select + scale only
            float qa = b2 ? q01[j] : q00[j];
            float qb = b2 ? q11[j] : q10[j];
            P[j] = (b1 ? qb : qa) * scale;
        }
    };

#pragma unroll 1
    for (int b = 0; b < CPB; b++) {
        round2(4 * b,     r1, -1);
        round2(4 * b + 2, r3, (b + 1 < CPB) ? b + 1 : -1);
    }

    // ---- epilogue: final inner = sum w*P (true value * 2^Kexp), outputs ----
    float sf = 0.f;
#pragma unroll
    for (int j = 0; j < KPJ; j++) {
        int k = kst + j;
        float w = (k < m || k >= MM) ? 0.f : ((k == m) ? 1.f : 2.f);
        sf += w * P[j];
    }
#pragma unroll
    for (int o = 16; o; o >>= 1) sf += __shfl_xor_sync(0xffffffffu, sf, o);
    if (lane == 0) prt[32 + wid] = sf;
    __syncthreads();

    if (tid < LL) out[n * LL + tid] = (float)((bits >> tid) & 1ull);
    if (tid == 0) {
        double Sf = (double)((prt[32] + prt[33]) + (prt[34] + prt[35]));
        double pmv = ldexp(fabs(Sf), Kexp) / (double)denom0;
        out[NN * LL + n] = (float)pmv;
    }
}

extern "C" void kernel_launch(void* const* d_in, const int* in_sizes, int n_in,
                              void* d_out, int out_size) {
    const float* inp    = (const float*)d_in[0];   // (N,L)
    const float* theta  = (const float*)d_in[1];   // (L,M)
    const float* coef   = (const float*)d_in[2];   // (M,)
    const float* rand_u = (const float*)d_in[3];   // (L,N)
    float* out = (float*)d_out;

    static int smem_set = 0;
    if (!smem_set) {
        cudaFuncSetAttribute(fused_kernel,
                             cudaFuncAttributeMaxDynamicSharedMemorySize,
                             SMEMF * (int)sizeof(float));
        smem_set = 1;
    }
    fused_kernel<<<NN, NT, SMEMF * sizeof(float)>>>(inp, theta, coef, rand_u, out);
}